// round 14
// baseline (speedup 1.0000x reference)
#include <cuda_runtime.h>
#include <cuda_fp16.h>
#include <math.h>
#include <stdint.h>

#define BATCH 8
#define CIN   256
#define NPIX  16384
#define HEADS 4
#define DH    32
#define HID   128

// ---------------- scratch (device globals; no allocation allowed) ------------
__device__ __half g_xh[(long)BATCH * CIN * NPIX];     // x in fp16 (written by k_fused1)
__device__ __half g_wh[256 * 256];                    // W_kv in fp16
__device__ __half g_wtoth[BATCH * 256 * 256];         // per-batch effective weight (fp16)
__device__ float  g_ctx[BATCH * HEADS * DH * DH];     // 32768
__device__ float  g_z[BATCH * HEADS * DH];            // 1024
__device__ float  g_weff[BATCH * 256 * HID];          // holds P[b][128][256]

__device__ __forceinline__ uint32_t cvt_tf32(float x) {
    uint32_t u;
    asm("cvt.rna.tf32.f32 %0, %1;" : "=r"(u) : "f"(x));
    return u;
}
__device__ __forceinline__ uint32_t smem_u32(const void* p) {
    uint32_t a;
    asm("{ .reg .u64 t; cvta.to.shared.u64 t, %1; cvt.u32.u64 %0, t; }" : "=r"(a) : "l"(p));
    return a;
}
#define CP16(dst, src) \
    asm volatile("cp.async.cg.shared.global [%0], [%1], 16;" :: "r"(dst), "l"(src) : "memory")
#define HMMA(acc, a0, a1, a2, a3, b0, b1) \
    asm volatile( \
        "mma.sync.aligned.m16n8k16.row.col.f32.f16.f16.f32 " \
        "{%0,%1,%2,%3},{%4,%5,%6,%7},{%8,%9},{%0,%1,%2,%3};" \
        : "+f"(acc[0]), "+f"(acc[1]), "+f"(acc[2]), "+f"(acc[3]) \
        : "r"(a0), "r"(a1), "r"(a2), "r"(a3), "r"(b0), "r"(b1))

// ---------------- init: zero ALL accumulators + convert W_kv to fp16 ---------
__global__ void k_init(const float* __restrict__ wkv) {
    int i = blockIdx.x * blockDim.x + threadIdx.x;   // 128*256 = 32768
    if (i < 16384) {
        float4 v = ((const float4*)wkv)[i];
        __half2 h0 = __floats2half2_rn(v.x, v.y);
        __half2 h1 = __floats2half2_rn(v.z, v.w);
        uint2 u = { *(uint32_t*)&h0, *(uint32_t*)&h1 };
        ((uint2*)g_wh)[i] = u;
    }
    g_ctx[i] = 0.f;
    if (i < BATCH * HEADS * DH) g_z[i] = 0.f;
}

// =============================================================================
// FUSED kernel (R11-exact, 187.1us proven): kv-GEMM + softmax-context.
//   CTA: 256 ch x 128 px, K=256, 8 warps (4M x 2N), warp tile 64x64.
//   fp32-B direct-LDS fragment feed; emits fp16 x once; epilogue ctx mma.
// =============================================================================
#define F_AST   80
#define F_A_ST  (256 * F_AST)
#define F_BLDW  132
#define F_B_ST  (32 * F_BLDW * 4)
#define F_B_OFF (2 * F_A_ST)
#define SMEM_F  (F_B_OFF + 2 * F_B_ST)   // 74752
#define EV_LDH  136

__global__ __launch_bounds__(256, 1)
void k_fused1(const __half* __restrict__ W, const float* __restrict__ X)
{
    extern __shared__ char smem[];
    uint32_t sb = smem_u32(smem);
    int tid = threadIdx.x, wid = tid >> 5, lane = tid & 31;
    int g4 = lane >> 2, q = lane & 3;
    int rowoff = (lane & 7) + ((lane >> 3) & 1) * 8;
    int colsel = (lane >> 4) * 8;
    int b = blockIdx.y;
    long n0 = (long)blockIdx.x * 128;
    const float* Xb = X + (long)b * CIN * NPIX;
    __half* XHb = g_xh + (long)b * CIN * NPIX;

    int wm = (wid >> 1) * 64;   // 0,64,128,192 (ch)
    int wn = (wid & 1) * 64;    // 0,64 (px)

    float acc[4][8][4];
#pragma unroll
    for (int i = 0; i < 4; i++)
#pragma unroll
        for (int j = 0; j < 8; j++)
#pragma unroll
            for (int r = 0; r < 4; r++) acc[i][j][r] = 0.f;

#define F_LOAD(buf, k0) do {                                                    \
        uint32_t abase_ = sb + (buf) * F_A_ST;                                  \
        uint32_t bbase_ = sb + F_B_OFF + (buf) * F_B_ST;                        \
        _Pragma("unroll")                                                       \
        for (int i_ = 0; i_ < 4; i_++) {                                        \
            int f_ = i_ * 256 + tid;                                            \
            int r_ = f_ >> 2, c_ = f_ & 3;                                      \
            CP16(abase_ + r_ * F_AST + c_ * 16, W + (long)r_ * 256 + (k0) + c_ * 8); \
        }                                                                       \
        _Pragma("unroll")                                                       \
        for (int i_ = 0; i_ < 4; i_++) {                                        \
            int f_ = i_ * 256 + tid;                                            \
            int r_ = f_ >> 5, c_ = f_ & 31;                                     \
            CP16(bbase_ + r_ * (F_BLDW * 4) + c_ * 16,                          \
                 Xb + (long)((k0) + r_) * NPIX + n0 + c_ * 4);                  \
        }                                                                       \
        asm volatile("cp.async.commit_group;" ::: "memory");                    \
    } while (0)

    F_LOAD(0, 0);

#pragma unroll 1
    for (int t = 0; t < 8; t++) {
        if (t < 7) F_LOAD((t + 1) & 1, (t + 1) * 32);
        if (t < 7) { asm volatile("cp.async.wait_group 1;" ::: "memory"); }
        else       { asm volatile("cp.async.wait_group 0;" ::: "memory"); }
        __syncthreads();

        const float* Bst = (const float*)(smem + F_B_OFF + (t & 1) * F_B_ST);

        // ---- emit converted fp16 x tile (once per element)
#pragma unroll
        for (int i = 0; i < 2; i++) {
            int f = i * 256 + tid;
            int r = f >> 4, c = f & 15;
            const float* src = &Bst[r * F_BLDW + c * 8];
            uint4 u;
            __half2* uh = (__half2*)&u;
#pragma unroll
            for (int j = 0; j < 4; j++)
                uh[j] = __floats2half2_rn(src[2 * j], src[2 * j + 1]);
            *(uint4*)&XHb[(long)(t * 32 + r) * NPIX + n0 + c * 8] = u;
        }

        uint32_t abase = sb + (t & 1) * F_A_ST;
#pragma unroll
        for (int ks = 0; ks < 32; ks += 16) {
            uint32_t af[4][4];
#pragma unroll
            for (int mf = 0; mf < 4; mf++) {
                uint32_t addr = abase + (uint32_t)((wm + mf * 16 + rowoff) * F_AST
                                                   + (ks + colsel) * 2);
                asm volatile(
                    "ldmatrix.sync.aligned.m8n8.x4.shared.b16 {%0,%1,%2,%3}, [%4];"
                    : "=r"(af[mf][0]), "=r"(af[mf][1]), "=r"(af[mf][2]), "=r"(af[mf][3])
                    : "r"(addr));
            }
#pragma unroll
            for (int nf = 0; nf < 8; nf++) {
                int n = wn + nf * 8 + g4;
                float x0 = Bst[(ks + 2 * q)     * F_BLDW + n];
                float x1 = Bst[(ks + 2 * q + 1) * F_BLDW + n];
                float x2 = Bst[(ks + 2 * q + 8) * F_BLDW + n];
                float x3 = Bst[(ks + 2 * q + 9) * F_BLDW + n];
                __half2 hb0 = __floats2half2_rn(x0, x1);
                __half2 hb1 = __floats2half2_rn(x2, x3);
                uint32_t b0 = *(uint32_t*)&hb0;
                uint32_t b1 = *(uint32_t*)&hb1;
#pragma unroll
                for (int mf = 0; mf < 4; mf++)
                    HMMA(acc[mf][nf], af[mf][0], af[mf][1], af[mf][2], af[mf][3], b0, b1);
            }
        }
        __syncthreads();
    }

    // ===================== fused context epilogue =====================
    __half* EV = (__half*)smem;
    int isk = (wm < 128);
#pragma unroll
    for (int mf = 0; mf < 4; mf++) {
        int mrow = wm + mf * 16 + g4;
#pragma unroll
        for (int nf = 0; nf < 8; nf++) {
            int nc = wn + nf * 8 + 2 * q;
            float v0 = acc[mf][nf][0], v1 = acc[mf][nf][1];
            float v2 = acc[mf][nf][2], v3 = acc[mf][nf][3];
            if (isk) {
                v0 = __expf(v0); v1 = __expf(v1);
                v2 = __expf(v2); v3 = __expf(v3);
            }
            *(__half2*)&EV[mrow * EV_LDH + nc]       = __floats2half2_rn(v0, v1);
            *(__half2*)&EV[(mrow + 8) * EV_LDH + nc] = __floats2half2_rn(v2, v3);
        }
    }
    __syncthreads();

    int h = wid >> 1, p = wid & 1;
    const __half* Ek = EV + (h * 32) * EV_LDH;
    const __half* Vv = EV + (128 + h * 32) * EV_LDH;
    float c2[2][4][4];
    float z2[2][4];
#pragma unroll
    for (int i = 0; i < 2; i++) {
#pragma unroll
        for (int j = 0; j < 4; j++)
#pragma unroll
            for (int r = 0; r < 4; r++) c2[i][j][r] = 0.f;
#pragma unroll
        for (int r = 0; r < 4; r++) z2[i][r] = 0.f;
    }
    const uint32_t ONES = 0x3C003C00u;

#pragma unroll
    for (int ks = 0; ks < 64; ks += 16) {
        int fc = p * 64 + ks + 2 * q;
#pragma unroll
        for (int mf = 0; mf < 2; mf++) {
            int d0 = mf * 16 + g4;
            uint32_t a0 = *(const uint32_t*)&Ek[d0 * EV_LDH + fc];
            uint32_t a1 = *(const uint32_t*)&Ek[(d0 + 8) * EV_LDH + fc];
            uint32_t a2 = *(const uint32_t*)&Ek[d0 * EV_LDH + fc + 8];
            uint32_t a3 = *(const uint32_t*)&Ek[(d0 + 8) * EV_LDH + fc + 8];
            HMMA(z2[mf], a0, a1, a2, a3, ONES, ONES);
#pragma unroll
            for (int nf = 0; nf < 4; nf++) {
                int e0 = nf * 8 + g4;
                uint32_t b0 = *(const uint32_t*)&Vv[e0 * EV_LDH + fc];
                uint32_t b1 = *(const uint32_t*)&Vv[e0 * EV_LDH + fc + 8];
                HMMA(c2[mf][nf], a0, a1, a2, a3, b0, b1);
            }
        }
    }
    __syncthreads();

    if (q == 0) {
        float* zp = g_z + (b * HEADS + h) * DH;
        atomicAdd(&zp[g4],      z2[0][0]);
        atomicAdd(&zp[g4 + 8],  z2[0][2]);
        atomicAdd(&zp[g4 + 16], z2[1][0]);
        atomicAdd(&zp[g4 + 24], z2[1][2]);
    }

    float* red = (float*)smem + wid * 1024;
#pragma unroll
    for (int mf = 0; mf < 2; mf++)
#pragma unroll
        for (int nf = 0; nf < 4; nf++) {
            int dd = mf * 16 + g4, ee = nf * 8 + 2 * q;
            red[dd * 32 + ee]           = c2[mf][nf][0];
            red[dd * 32 + ee + 1]       = c2[mf][nf][1];
            red[(dd + 8) * 32 + ee]     = c2[mf][nf][2];
            red[(dd + 8) * 32 + ee + 1] = c2[mf][nf][3];
        }
    __syncthreads();

    const float* rall = (const float*)smem;
#pragma unroll
    for (int j = tid; j < 4096; j += 256) {
        int hh = j >> 10, e = j & 1023;
        float s = rall[(2 * hh) * 1024 + e] + rall[(2 * hh + 1) * 1024 + e];
        atomicAdd(&g_ctx[((long)b * HEADS + hh) * 1024 + e], s);
    }
}

// =============================================================================
// k_P: P[b][h*32+e][c] = sum_d (ctx[h][d][e]/z[d]) * W_q[h*32+d][c]
// grid (BATCH, HEADS), 256 thr. Replaces k_weff (re-associated fold).
// =============================================================================
__global__ __launch_bounds__(256)
void k_P(const float* __restrict__ wq)
{
    __shared__ float ctxn[32][33];
    __shared__ float zinv[32];
    int b = blockIdx.x, h = blockIdx.y;
    int tid = threadIdx.x;
    if (tid < 32) zinv[tid] = 1.0f / g_z[(b * HEADS + h) * DH + tid];
    __syncthreads();
    for (int i = tid; i < 1024; i += 256) {
        int d = i >> 5;
        ctxn[d][i & 31] = g_ctx[((long)b * HEADS + h) * 1024 + i] * zinv[d];
    }
    __syncthreads();

    int r  = tid >> 3;           // e-index 0..31
    int c0 = (tid & 7) * 32;     // 32 cols per thread
    float s[32];
#pragma unroll
    for (int j = 0; j < 32; j++) s[j] = 0.f;

#pragma unroll 4
    for (int d = 0; d < 32; d++) {
        float a = ctxn[d][r];
        const float* wrow = wq + (h * 32 + d) * 256 + c0;
#pragma unroll
        for (int j = 0; j < 32; j += 4) {
            float4 w4 = *(const float4*)&wrow[j];
            s[j + 0] = fmaf(a, w4.x, s[j + 0]);
            s[j + 1] = fmaf(a, w4.y, s[j + 1]);
            s[j + 2] = fmaf(a, w4.z, s[j + 2]);
            s[j + 3] = fmaf(a, w4.w, s[j + 3]);
        }
    }
    float* Pp = g_weff + (long)b * 32768 + (h * 32 + r) * 256 + c0;
#pragma unroll
    for (int j = 0; j < 32; j += 4)
        *(float4*)&Pp[j] = make_float4(s[j], s[j + 1], s[j + 2], s[j + 3]);
}

// =============================================================================
// fp16 x fp16 cp.async GEMM (round-8 kernel) — final GEMM only
// =============================================================================
#define H_A_BUF 18432
#define H_B_BUF 17408
#define SMEM_H (2 * H_A_BUF + 2 * H_B_BUF)

__device__ __forceinline__ void g2s_tile_ff(uint32_t sb, int buf,
                                            const __half* Arow, const __half* Xb,
                                            long n0, int k0) {
    int tid = threadIdx.x;
    uint32_t abase = sb + buf * H_A_BUF;
    uint32_t bbase = sb + 2 * H_A_BUF + buf * H_B_BUF;
#pragma unroll
    for (int i = 0; i < 4; i++) {
        int f = i * 256 + tid;
        int r = f >> 3, c = f & 7;
        CP16(abase + r * 144 + c * 16, Arow + (long)r * 256 + k0 + c * 8);
    }
#pragma unroll
    for (int i = 0; i < 4; i++) {
        int f = i * 256 + tid;
        int r = f >> 4, c = f & 15;
        CP16(bbase + r * 272 + c * 16, Xb + (long)(k0 + r) * NPIX + n0 + c * 8);
    }
    asm volatile("cp.async.commit_group;" ::: "memory");
}

__global__ __launch_bounds__(256, 2)
void k_hgemm_ff(const __half* __restrict__ A, long sA,
                const __half* __restrict__ X, long sX,
                float* __restrict__ C, long sC,
                const float* __restrict__ bias)
{
    extern __shared__ char smem[];
    uint32_t sb = smem_u32(smem);

    int b = blockIdx.z;
    const __half* Ab = A + (long)b * sA + (long)blockIdx.y * 128 * 256;
    const __half* Xb = X + (long)b * sX;
    long n0 = (long)blockIdx.x * 128;
    int m0 = blockIdx.y * 128;

    int tid  = threadIdx.x;
    int wid  = tid >> 5, lane = tid & 31;
    int g4   = lane >> 2, q = lane & 3;
    int wm   = (wid >> 2) * 64;
    int wn   = (wid & 3) * 32;
    int rowoff = (lane & 7) + ((lane >> 3) & 1) * 8;
    int colsel = (lane >> 4) * 8;

    float acc[4][4][4];
#pragma unroll
    for (int i = 0; i < 4; i++)
#pragma unroll
        for (int j = 0; j < 4; j++)
#pragma unroll
            for (int r = 0; r < 4; r++) acc[i][j][r] = 0.f;

    g2s_tile_ff(sb, 0, Ab, Xb, n0, 0);

#pragma unroll 1
    for (int t = 0; t < 4; t++) {
        if (t < 3) g2s_tile_ff(sb, (t + 1) & 1, Ab, Xb, n0, (t + 1) * 64);
        if (t < 3) { asm volatile("cp.async.wait_group 1;" ::: "memory"); }
        else       { asm volatile("cp.async.wait_group 0;" ::: "memory"); }
        __syncthreads();

        uint32_t abase = sb + (t & 1) * H_A_BUF;
        uint32_t bbase = sb + 2 * H_A_BUF + (t & 1) * H_B_BUF;
#pragma unroll
        for (int ks = 0; ks < 64; ks += 16) {
            uint32_t af[4][4];
#pragma unroll
            for (int mf = 0; mf < 4; mf++) {
                uint32_t addr = abase + (uint32_t)((wm + mf * 16 + rowoff) * 144
                                                   + (ks + colsel) * 2);
                asm volatile(
                    "ldmatrix.sync.aligned.m8n8.x4.shared.b16 {%0,%1,%2,%3}, [%4];"
                    : "=r"(af[mf][0]), "=r"(af[mf][1]), "=r"(af[mf][2]), "=r"(af[mf][3])
                    : "r"(addr));
            }
            uint32_t bf[2][4];
#pragma unroll
            for (int np = 0; np < 2; np++) {
                uint32_t addr = bbase + (uint32_t)((ks + rowoff) * 272
                                                   + (wn + np * 16 + colsel) * 2);
                asm volatile(
                    "ldmatrix.sync.aligned.m8n8.x4.trans.shared.b16 {%0,%1,%2,%3}, [%4];"
                    : "=r"(bf[np][0]), "=r"(bf[np][1]), "=r"(bf[np][2]), "=r"(bf[np][3])
                    : "r"(addr));
            }
#pragma unroll
            for (int nf = 0; nf < 4; nf++) {
                uint32_t b0 = bf[nf >> 1][(nf & 1) * 2];
                uint32_t b1 = bf[nf >> 1][(nf & 1) * 2 + 1];
#pragma unroll
                for (int mf = 0; mf < 4; mf++)
                    HMMA(acc[mf][nf], af[mf][0], af[mf][1], af[mf][2], af[mf][3], b0, b1);
            }
        }
        __syncthreads();
    }

#pragma unroll
    for (int mf = 0; mf < 4; mf++) {
        long mrow = m0 + wm + mf * 16 + g4;
        float bv0 = bias[mrow];
        float bv1 = bias[mrow + 8];
#pragma unroll
        for (int nf = 0; nf < 4; nf++) {
            long nc = n0 + wn + nf * 8 + 2 * q;
            float2 v0 = { acc[mf][nf][0] + bv0, acc[mf][nf][1] + bv0 };
            float2 v1 = { acc[mf][nf][2] + bv1, acc[mf][nf][3] + bv1 };
            float* Cf = C + (long)b * sC;
            *(float2*)&Cf[mrow * NPIX + nc]       = v0;
            *(float2*)&Cf[(mrow + 8) * NPIX + nc] = v1;
        }
    }
}

// ---------------- tf32 mma SGEMM -> fp16 out (fold GEMM: wtot = w_out @ P) ---
__global__ __launch_bounds__(256, 2)
void k_sgemm_tc(const float* __restrict__ A, long sA,
                const float* __restrict__ X, long sX,
                __half* __restrict__ C, long sC,
                int M, int K, int N)
{
    const int BM = 128, BN = 128, BK = 32;
    __shared__ uint32_t As[BK][BM + 4];
    __shared__ uint32_t Bs[BK][BN + 4];

    int b = blockIdx.z;
    const float* Ab = A + (long)b * sA;
    const float* Xb = X + (long)b * sX;
    __half*      Cb = C + (long)b * sC;
    int m0 = blockIdx.y * BM, n0 = blockIdx.x * BN;
    int tid  = threadIdx.x;
    int wid  = tid >> 5, lane = tid & 31;
    int g4   = lane >> 2, q = lane & 3;
    int wm   = (wid >> 2) * 64;
    int wn   = (wid & 3) * 32;

    float acc[4][4][4];
#pragma unroll
    for (int i = 0; i < 4; i++)
#pragma unroll
        for (int j = 0; j < 4; j++)
#pragma unroll
            for (int r = 0; r < 4; r++) acc[i][j][r] = 0.f;

    for (int k0 = 0; k0 < K; k0 += BK) {
#pragma unroll
        for (int i = 0; i < 4; i++) {
            int f  = i * 256 + tid;
            int m  = f >> 3, k4 = (f & 7) << 2;
            float4 v = *(const float4*)&Ab[(long)(m0 + m) * K + k0 + k4];
            As[k4 + 0][m] = cvt_tf32(v.x); As[k4 + 1][m] = cvt_tf32(v.y);
            As[k4 + 2][m] = cvt_tf32(v.z); As[k4 + 3][m] = cvt_tf32(v.w);
        }
#pragma unroll
        for (int i = 0; i < 4; i++) {
            int f  = i * 256 + tid;
            int kk = f >> 5, n4 = (f & 31) << 2;
            float4 v = *(const float4*)&Xb[(long)(k0 + kk) * N + n0 + n4];
            uint4 u;
            u.x = cvt_tf32(v.x); u.y = cvt_tf32(v.y);
            u.z = cvt_tf32(v.z); u.w = cvt_tf32(v.w);
            *(uint4*)&Bs[kk][n4] = u;
        }
        __syncthreads();

#pragma unroll
        for (int ks = 0; ks < BK; ks += 8) {
            uint32_t af[4][4];
#pragma unroll
            for (int mf = 0; mf < 4; mf++) {
                int mb = wm + mf * 16;
                af[mf][0] = As[ks + q    ][mb + g4    ];
                af[mf][1] = As[ks + q    ][mb + g4 + 8];
                af[mf][2] = As[ks + q + 4][mb + g4    ];
                af[mf][3] = As[ks + q + 4][mb + g4 + 8];
            }
#pragma unroll
            for (int nf = 0; nf < 4; nf++) {
                int nb = wn + nf * 8;
                uint32_t b0 = Bs[ks + q    ][nb + g4];
                uint32_t b1 = Bs[ks + q + 4][nb + g4];
#pragma unroll
                for (int mf = 0; mf < 4; mf++) {
                    asm volatile(
                        "mma.sync.aligned.m16n8k8.row.col.f32.tf32.tf32.f32 "
                        "{%0,%1,%2,%3},{%4,%5,%6,%7},{%8,%9},{%0,%1,%2,%3};"
                        : "+f"(acc[mf][nf][0]), "+f"(acc[mf][nf][1]),
                          "+f"(acc[mf][nf][2]), "+f"(acc[mf][nf][3])
                        : "r"(af[mf][0]), "r"(af[mf][1]),
                          "r"(af[mf][2]), "r"(af[mf][3]),
                          "r"(b0), "r"(b1));
                }
            }
        }
        __syncthreads();
    }

#pragma unroll
    for (int mf = 0; mf < 4; mf++) {
        int mrow = m0 + wm + mf * 16 + g4;
#pragma unroll
        for (int nf = 0; nf < 4; nf++) {
            int nc = n0 + wn + nf * 8 + 2 * q;
            *(__half2*)&Cb[(long)mrow * N + nc] =
                __floats2half2_rn(acc[mf][nf][0], acc[mf][nf][1]);
            *(__half2*)&Cb[(long)(mrow + 8) * N + nc] =
                __floats2half2_rn(acc[mf][nf][2], acc[mf][nf][3]);
        }
    }
}

// ---------------- launch --------------------------------------------------
extern "C" void kernel_launch(void* const* d_in, const int* in_sizes, int n_in,
                              void* d_out, int out_size)
{
    const float *x = nullptr, *w_qkv = nullptr, *w_out = nullptr, *b_out = nullptr;
    for (int i = 0; i < n_in; i++) {
        const float* p = (const float*)d_in[i];
        if      (in_sizes[i] == BATCH * CIN * NPIX) x     = p;
        else if (in_sizes[i] == 3 * HID * CIN)      w_qkv = p;
        else if (in_sizes[i] == CIN * HID)          w_out = p;
        else if (in_sizes[i] == CIN)                b_out = p;
    }
    float* out = (float*)d_out;

    __half *xh, *wh, *wtoth;
    float *weff;
    cudaGetSymbolAddress((void**)&xh,    g_xh);
    cudaGetSymbolAddress((void**)&wh,    g_wh);
    cudaGetSymbolAddress((void**)&wtoth, g_wtoth);
    cudaGetSymbolAddress((void**)&weff,  g_weff);

    cudaFuncSetAttribute(k_fused1,
                         cudaFuncAttributeMaxDynamicSharedMemorySize, SMEM_F);
    cudaFuncSetAttribute(k_hgemm_ff,
                         cudaFuncAttributeMaxDynamicSharedMemorySize, SMEM_H);

    // 0) zero ALL accumulators + convert W_kv
    k_init<<<128, 256>>>(w_qkv + 128 * CIN);

    // 1) FUSED: kv-GEMM + exp + context + z; also emits fp16 x (R11-exact)
    k_fused1<<<dim3(NPIX / 128, BATCH), 256, SMEM_F>>>(wh, x);

    // 2) P = ctxn^T @ W_q per head (replaces k_weff)
    k_P<<<dim3(BATCH, HEADS), 256>>>(w_qkv);

    // 3) wtot = w_out @ P  -> fp16 (A shared across batches: sA=0)
    k_sgemm_tc<<<dim3(2, 2, BATCH), 256>>>(
        w_out, 0,
        weff, (long)256 * HID,
        wtoth, (long)256 * 256,
        256, HID, 256);

    // 4) y[b] = W_total[b] @ x[b] + b_out  (fast fp16 x fp16 GEMM)
    k_hgemm_ff<<<dim3(NPIX / 128, 2, BATCH), 256, SMEM_H>>>(
        wtoth, (long)256 * 256,
        xh, (long)CIN * NPIX,
        out, (long)256 * NPIX,
        b_out);
}

// round 15
// speedup vs baseline: 1.0833x; 1.0833x over previous
#include <cuda_runtime.h>
#include <cuda_fp16.h>
#include <math.h>
#include <stdint.h>

#define BATCH 8
#define CIN   256
#define NPIX  16384
#define HEADS 4
#define DH    32
#define HID   128

// ---------------- scratch (device globals; no allocation allowed) ------------
__device__ __half g_xh[(long)BATCH * CIN * NPIX];     // x in fp16 (written by k_fused1)
__device__ __half g_wh[256 * 256];                    // W_kv in fp16
__device__ __half g_wtoth[BATCH * 256 * 256];         // per-batch effective weight (fp16)
__device__ float  g_ctx[BATCH * HEADS * DH * DH];     // 32768
__device__ float  g_z[BATCH * HEADS * DH];            // 1024
__device__ float  g_weff[BATCH * 256 * HID];          // holds P[b][128][256]

__device__ __forceinline__ uint32_t cvt_tf32(float x) {
    uint32_t u;
    asm("cvt.rna.tf32.f32 %0, %1;" : "=r"(u) : "f"(x));
    return u;
}
__device__ __forceinline__ uint32_t smem_u32(const void* p) {
    uint32_t a;
    asm("{ .reg .u64 t; cvta.to.shared.u64 t, %1; cvt.u32.u64 %0, t; }" : "=r"(a) : "l"(p));
    return a;
}
#define CP16(dst, src) \
    asm volatile("cp.async.cg.shared.global [%0], [%1], 16;" :: "r"(dst), "l"(src) : "memory")
#define HMMA(acc, a0, a1, a2, a3, b0, b1) \
    asm volatile( \
        "mma.sync.aligned.m16n8k16.row.col.f32.f16.f16.f32 " \
        "{%0,%1,%2,%3},{%4,%5,%6,%7},{%8,%9},{%0,%1,%2,%3};" \
        : "+f"(acc[0]), "+f"(acc[1]), "+f"(acc[2]), "+f"(acc[3]) \
        : "r"(a0), "r"(a1), "r"(a2), "r"(a3), "r"(b0), "r"(b1))

// ---------------- init: zero ALL accumulators + convert W_kv to fp16 ---------
__global__ void k_init(const float* __restrict__ wkv) {
    int i = blockIdx.x * blockDim.x + threadIdx.x;   // 128*256 = 32768
    if (i < 16384) {
        float4 v = ((const float4*)wkv)[i];
        __half2 h0 = __floats2half2_rn(v.x, v.y);
        __half2 h1 = __floats2half2_rn(v.z, v.w);
        uint2 u = { *(uint32_t*)&h0, *(uint32_t*)&h1 };
        ((uint2*)g_wh)[i] = u;
    }
    g_ctx[i] = 0.f;
    if (i < BATCH * HEADS * DH) g_z[i] = 0.f;
}

// =============================================================================
// FUSED kernel, resident-W version: kv-GEMM + softmax-context.
//   W (256x256 fp16, 528B-stride smem, 132KB) loaded ONCE per CTA; CTA then
//   processes NL=4 pixel tiles of 128, streaming only X (fp32, cp.async).
//   Inner loop identical to R11 (ldmatrix A, fp32-B direct-LDS fragments).
//   Grid (32, BATCH) = 256 CTAs -> W L2 traffic 128MB -> 33MB.
// =============================================================================
#define FW_LDB  528                          // W row stride bytes (256+8 halves)
#define FW_RES  (256 * FW_LDB)               // 135168
#define F_BLDW  132                          // fp32 X stage row stride (floats)
#define F_B_ST  (32 * F_BLDW * 4)            // 16896 per stage
#define SMEM_F  (FW_RES + 69632)             // 204800 (EV epilogue overlays B stages)
#define EV_LDH  136
#define F_NL    4

__global__ __launch_bounds__(256, 1)
void k_fused1(const __half* __restrict__ W, const float* __restrict__ X)
{
    extern __shared__ char smem[];
    uint32_t sb = smem_u32(smem);
    int tid = threadIdx.x, wid = tid >> 5, lane = tid & 31;
    int g4 = lane >> 2, q = lane & 3;
    int rowoff = (lane & 7) + ((lane >> 3) & 1) * 8;
    int colsel = (lane >> 4) * 8;
    int b = blockIdx.y;
    const float* Xb = X + (long)b * CIN * NPIX;
    __half* XHb = g_xh + (long)b * CIN * NPIX;

    int wm = (wid >> 1) * 64;   // 0,64,128,192 (ch)
    int wn = (wid & 1) * 64;    // 0,64 (px)
    int h = wid >> 1, p = wid & 1;
    const uint32_t ONES = 0x3C003C00u;

    // ---- load W resident: 256 rows x 256 halves, 528B stride (one commit)
#pragma unroll
    for (int i = 0; i < 32; i++) {
        int f = i * 256 + tid;
        int r = f >> 5, c = f & 31;
        CP16(sb + r * FW_LDB + c * 16, W + (long)r * 256 + c * 8);
    }
    asm volatile("cp.async.commit_group;" ::: "memory");

#define FB_LOAD(buf, k0, n0) do {                                               \
        uint32_t bbase_ = sb + FW_RES + (buf) * F_B_ST;                         \
        _Pragma("unroll")                                                       \
        for (int i_ = 0; i_ < 4; i_++) {                                        \
            int f_ = i_ * 256 + tid;                                            \
            int r_ = f_ >> 5, c_ = f_ & 31;                                     \
            CP16(bbase_ + r_ * (F_BLDW * 4) + c_ * 16,                          \
                 Xb + (long)((k0) + r_) * NPIX + (n0) + c_ * 4);                \
        }                                                                       \
        asm volatile("cp.async.commit_group;" ::: "memory");                    \
    } while (0)

#pragma unroll 1
    for (int nt = 0; nt < F_NL; nt++) {
        long n0 = ((long)blockIdx.x * F_NL + nt) * 128;

        float acc[4][8][4];
#pragma unroll
        for (int i = 0; i < 4; i++)
#pragma unroll
            for (int j = 0; j < 8; j++)
#pragma unroll
                for (int r = 0; r < 4; r++) acc[i][j][r] = 0.f;

        FB_LOAD(0, 0, n0);

#pragma unroll 1
        for (int t = 0; t < 8; t++) {
            if (t < 7) FB_LOAD((t + 1) & 1, (t + 1) * 32, n0);
            if (t < 7) { asm volatile("cp.async.wait_group 1;" ::: "memory"); }
            else       { asm volatile("cp.async.wait_group 0;" ::: "memory"); }
            __syncthreads();

            const float* Bst = (const float*)(smem + FW_RES + (t & 1) * F_B_ST);

            // ---- emit converted fp16 x tile (once per element)
#pragma unroll
            for (int i = 0; i < 2; i++) {
                int f = i * 256 + tid;
                int r = f >> 4, c = f & 15;
                const float* src = &Bst[r * F_BLDW + c * 8];
                uint4 u;
                __half2* uh = (__half2*)&u;
#pragma unroll
                for (int j = 0; j < 4; j++)
                    uh[j] = __floats2half2_rn(src[2 * j], src[2 * j + 1]);
                *(uint4*)&XHb[(long)(t * 32 + r) * NPIX + n0 + c * 8] = u;
            }

#pragma unroll
            for (int ks = 0; ks < 32; ks += 16) {
                uint32_t af[4][4];
#pragma unroll
                for (int mf = 0; mf < 4; mf++) {
                    uint32_t addr = sb + (uint32_t)((wm + mf * 16 + rowoff) * FW_LDB
                                                    + (t * 32 + ks + colsel) * 2);
                    asm volatile(
                        "ldmatrix.sync.aligned.m8n8.x4.shared.b16 {%0,%1,%2,%3}, [%4];"
                        : "=r"(af[mf][0]), "=r"(af[mf][1]), "=r"(af[mf][2]), "=r"(af[mf][3])
                        : "r"(addr));
                }
#pragma unroll
                for (int nf = 0; nf < 8; nf++) {
                    int n = wn + nf * 8 + g4;
                    float x0 = Bst[(ks + 2 * q)     * F_BLDW + n];
                    float x1 = Bst[(ks + 2 * q + 1) * F_BLDW + n];
                    float x2 = Bst[(ks + 2 * q + 8) * F_BLDW + n];
                    float x3 = Bst[(ks + 2 * q + 9) * F_BLDW + n];
                    __half2 hb0 = __floats2half2_rn(x0, x1);
                    __half2 hb1 = __floats2half2_rn(x2, x3);
                    uint32_t b0 = *(uint32_t*)&hb0;
                    uint32_t b1 = *(uint32_t*)&hb1;
#pragma unroll
                    for (int mf = 0; mf < 4; mf++)
                        HMMA(acc[mf][nf], af[mf][0], af[mf][1], af[mf][2], af[mf][3], b0, b1);
                }
            }
            __syncthreads();
        }

        // ===== fused context epilogue (EV overlays B-stage region) =====
        __half* EV = (__half*)(smem + FW_RES);
        int isk = (wm < 128);
#pragma unroll
        for (int mf = 0; mf < 4; mf++) {
            int mrow = wm + mf * 16 + g4;
#pragma unroll
            for (int nf = 0; nf < 8; nf++) {
                int nc = wn + nf * 8 + 2 * q;
                float v0 = acc[mf][nf][0], v1 = acc[mf][nf][1];
                float v2 = acc[mf][nf][2], v3 = acc[mf][nf][3];
                if (isk) {
                    v0 = __expf(v0); v1 = __expf(v1);
                    v2 = __expf(v2); v3 = __expf(v3);
                }
                *(__half2*)&EV[mrow * EV_LDH + nc]       = __floats2half2_rn(v0, v1);
                *(__half2*)&EV[(mrow + 8) * EV_LDH + nc] = __floats2half2_rn(v2, v3);
            }
        }
        __syncthreads();

        const __half* Ek = EV + (h * 32) * EV_LDH;
        const __half* Vv = EV + (128 + h * 32) * EV_LDH;
        float c2[2][4][4];
        float z2[2][4];
#pragma unroll
        for (int i = 0; i < 2; i++) {
#pragma unroll
            for (int j = 0; j < 4; j++)
#pragma unroll
                for (int r = 0; r < 4; r++) c2[i][j][r] = 0.f;
#pragma unroll
            for (int r = 0; r < 4; r++) z2[i][r] = 0.f;
        }

#pragma unroll
        for (int ks = 0; ks < 64; ks += 16) {
            int fc = p * 64 + ks + 2 * q;
#pragma unroll
            for (int mf = 0; mf < 2; mf++) {
                int d0 = mf * 16 + g4;
                uint32_t a0 = *(const uint32_t*)&Ek[d0 * EV_LDH + fc];
                uint32_t a1 = *(const uint32_t*)&Ek[(d0 + 8) * EV_LDH + fc];
                uint32_t a2 = *(const uint32_t*)&Ek[d0 * EV_LDH + fc + 8];
                uint32_t a3 = *(const uint32_t*)&Ek[(d0 + 8) * EV_LDH + fc + 8];
                HMMA(z2[mf], a0, a1, a2, a3, ONES, ONES);
#pragma unroll
                for (int nf = 0; nf < 4; nf++) {
                    int e0 = nf * 8 + g4;
                    uint32_t b0 = *(const uint32_t*)&Vv[e0 * EV_LDH + fc];
                    uint32_t b1 = *(const uint32_t*)&Vv[e0 * EV_LDH + fc + 8];
                    HMMA(c2[mf][nf], a0, a1, a2, a3, b0, b1);
                }
            }
        }
        __syncthreads();   // all EV reads done before red overwrite

        if (q == 0) {
            float* zp = g_z + (b * HEADS + h) * DH;
            atomicAdd(&zp[g4],      z2[0][0]);
            atomicAdd(&zp[g4 + 8],  z2[0][2]);
            atomicAdd(&zp[g4 + 16], z2[1][0]);
            atomicAdd(&zp[g4 + 24], z2[1][2]);
        }

        float* red = (float*)(smem + FW_RES) + wid * 1024;
#pragma unroll
        for (int mf = 0; mf < 2; mf++)
#pragma unroll
            for (int nf = 0; nf < 4; nf++) {
                int dd = mf * 16 + g4, ee = nf * 8 + 2 * q;
                red[dd * 32 + ee]           = c2[mf][nf][0];
                red[dd * 32 + ee + 1]       = c2[mf][nf][1];
                red[(dd + 8) * 32 + ee]     = c2[mf][nf][2];
                red[(dd + 8) * 32 + ee + 1] = c2[mf][nf][3];
            }
        __syncthreads();

        const float* rall = (const float*)(smem + FW_RES);
#pragma unroll
        for (int j = tid; j < 4096; j += 256) {
            int hh = j >> 10, e = j & 1023;
            float s = rall[(2 * hh) * 1024 + e] + rall[(2 * hh + 1) * 1024 + e];
            atomicAdd(&g_ctx[((long)b * HEADS + hh) * 1024 + e], s);
        }
        __syncthreads();   // red/EV region reused as B stage next nt
    }
}

// =============================================================================
// k_P: P[b][h*32+e][c] = sum_d (ctx[h][d][e]/z[d]) * W_q[h*32+d][c]
// grid (BATCH, HEADS), 1024 thr.
// =============================================================================
__global__ __launch_bounds__(1024)
void k_P(const float* __restrict__ wq)
{
    __shared__ float ctxn[32][33];
    __shared__ float zinv[32];
    int b = blockIdx.x, h = blockIdx.y;
    int tid = threadIdx.x;
    if (tid < 32) zinv[tid] = 1.0f / g_z[(b * HEADS + h) * DH + tid];
    __syncthreads();
    {
        int d = tid >> 5;
        ctxn[d][tid & 31] = g_ctx[((long)b * HEADS + h) * 1024 + tid] * zinv[d];
    }
    __syncthreads();

    int e  = tid >> 5;          // 0..31
    int c0 = (tid & 31) * 8;    // 8 cols per thread
    float s[8];
#pragma unroll
    for (int j = 0; j < 8; j++) s[j] = 0.f;

#pragma unroll 8
    for (int d = 0; d < 32; d++) {
        float a = ctxn[d][e];
        const float* wrow = wq + (h * 32 + d) * 256 + c0;
        float4 w0 = *(const float4*)&wrow[0];
        float4 w1 = *(const float4*)&wrow[4];
        s[0] = fmaf(a, w0.x, s[0]); s[1] = fmaf(a, w0.y, s[1]);
        s[2] = fmaf(a, w0.z, s[2]); s[3] = fmaf(a, w0.w, s[3]);
        s[4] = fmaf(a, w1.x, s[4]); s[5] = fmaf(a, w1.y, s[5]);
        s[6] = fmaf(a, w1.z, s[6]); s[7] = fmaf(a, w1.w, s[7]);
    }
    float* Pp = g_weff + (long)b * 32768 + (h * 32 + e) * 256 + c0;
    *(float4*)&Pp[0] = make_float4(s[0], s[1], s[2], s[3]);
    *(float4*)&Pp[4] = make_float4(s[4], s[5], s[6], s[7]);
}

// =============================================================================
// fp16 x fp16 GEMM, resident-A version: each CTA loads its 128x256 A half
// once (528B stride, 66KB) and streams NL=4 n-tiles of B.
// grid (32, 2, BATCH) = 512 CTAs, 2 CTAs/SM.
// =============================================================================
#define H_ALD   528
#define H_ARES  (128 * H_ALD)              // 67584
#define H_B_ST  17408                      // 64 rows * 272B
#define SMEM_H  (H_ARES + 2 * H_B_ST)      // 102400
#define H_NL    4

__global__ __launch_bounds__(256, 2)
void k_hgemm_ff(const __half* __restrict__ A, long sA,
                const __half* __restrict__ X, long sX,
                float* __restrict__ C, long sC,
                const float* __restrict__ bias)
{
    extern __shared__ char smem[];
    uint32_t sb = smem_u32(smem);

    int b = blockIdx.z;
    const __half* Ab = A + (long)b * sA + (long)blockIdx.y * 128 * 256;
    const __half* Xb = X + (long)b * sX;
    float* Cf = C + (long)b * sC;
    int m0 = blockIdx.y * 128;

    int tid  = threadIdx.x;
    int wid  = tid >> 5, lane = tid & 31;
    int g4   = lane >> 2, q = lane & 3;
    int wm   = (wid >> 2) * 64;
    int wn   = (wid & 3) * 32;
    int rowoff = (lane & 7) + ((lane >> 3) & 1) * 8;
    int colsel = (lane >> 4) * 8;

    // ---- load A resident: 128 rows x 256 halves (one commit)
#pragma unroll
    for (int i = 0; i < 16; i++) {
        int f = i * 256 + tid;
        int r = f >> 5, c = f & 31;
        CP16(sb + r * H_ALD + c * 16, Ab + (long)r * 256 + c * 8);
    }
    asm volatile("cp.async.commit_group;" ::: "memory");

    float bv0[4], bv1[4];
#pragma unroll
    for (int mf = 0; mf < 4; mf++) {
        bv0[mf] = bias[m0 + wm + mf * 16 + g4];
        bv1[mf] = bias[m0 + wm + mf * 16 + g4 + 8];
    }

#define HB_LOAD(buf, k0, n0) do {                                               \
        uint32_t bbase_ = sb + H_ARES + (buf) * H_B_ST;                         \
        _Pragma("unroll")                                                       \
        for (int i_ = 0; i_ < 4; i_++) {                                        \
            int f_ = i_ * 256 + tid;                                            \
            int r_ = f_ >> 4, c_ = f_ & 15;                                     \
            CP16(bbase_ + r_ * 272 + c_ * 16,                                   \
                 Xb + (long)((k0) + r_) * NPIX + (n0) + c_ * 8);                \
        }                                                                       \
        asm volatile("cp.async.commit_group;" ::: "memory");                    \
    } while (0)

#pragma unroll 1
    for (int nt = 0; nt < H_NL; nt++) {
        long n0 = ((long)blockIdx.x * H_NL + nt) * 128;

        float acc[4][4][4];
#pragma unroll
        for (int i = 0; i < 4; i++)
#pragma unroll
            for (int j = 0; j < 4; j++)
#pragma unroll
                for (int r = 0; r < 4; r++) acc[i][j][r] = 0.f;

        HB_LOAD(0, 0, n0);

#pragma unroll 1
        for (int t = 0; t < 4; t++) {
            if (t < 3) HB_LOAD((t + 1) & 1, (t + 1) * 64, n0);
            if (t < 3) { asm volatile("cp.async.wait_group 1;" ::: "memory"); }
            else       { asm volatile("cp.async.wait_group 0;" ::: "memory"); }
            __syncthreads();

            uint32_t bbase = sb + H_ARES + (t & 1) * H_B_ST;
#pragma unroll
            for (int ks = 0; ks < 64; ks += 16) {
                uint32_t af[4][4];
#pragma unroll
                for (int mf = 0; mf < 4; mf++) {
                    uint32_t addr = sb + (uint32_t)((wm + mf * 16 + rowoff) * H_ALD
                                                    + (t * 64 + ks + colsel) * 2);
                    asm volatile(
                        "ldmatrix.sync.aligned.m8n8.x4.shared.b16 {%0,%1,%2,%3}, [%4];"
                        : "=r"(af[mf][0]), "=r"(af[mf][1]), "=r"(af[mf][2]), "=r"(af[mf][3])
                        : "r"(addr));
                }
                uint32_t bf[2][4];
#pragma unroll
                for (int np = 0; np < 2; np++) {
                    uint32_t addr = bbase + (uint32_t)((ks + rowoff) * 272
                                                       + (wn + np * 16 + colsel) * 2);
                    asm volatile(
                        "ldmatrix.sync.aligned.m8n8.x4.trans.shared.b16 {%0,%1,%2,%3}, [%4];"
                        : "=r"(bf[np][0]), "=r"(bf[np][1]), "=r"(bf[np][2]), "=r"(bf[np][3])
                        : "r"(addr));
                }
#pragma unroll
                for (int nf = 0; nf < 4; nf++) {
                    uint32_t b0 = bf[nf >> 1][(nf & 1) * 2];
                    uint32_t b1 = bf[nf >> 1][(nf & 1) * 2 + 1];
#pragma unroll
                    for (int mf = 0; mf < 4; mf++)
                        HMMA(acc[mf][nf], af[mf][0], af[mf][1], af[mf][2], af[mf][3], b0, b1);
                }
            }
            __syncthreads();
        }

#pragma unroll
        for (int mf = 0; mf < 4; mf++) {
            long mrow = m0 + wm + mf * 16 + g4;
#pragma unroll
            for (int nf = 0; nf < 4; nf++) {
                long nc = n0 + wn + nf * 8 + 2 * q;
                float2 v0 = { acc[mf][nf][0] + bv0[mf], acc[mf][nf][1] + bv0[mf] };
                float2 v1 = { acc[mf][nf][2] + bv1[mf], acc[mf][nf][3] + bv1[mf] };
                *(float2*)&Cf[mrow * NPIX + nc]       = v0;
                *(float2*)&Cf[(mrow + 8) * NPIX + nc] = v1;
            }
        }
    }
}

// ---------------- tf32 mma SGEMM -> fp16 out (fold GEMM: wtot = w_out @ P) ---
__global__ __launch_bounds__(256, 2)
void k_sgemm_tc(const float* __restrict__ A, long sA,
                const float* __restrict__ X, long sX,
                __half* __restrict__ C, long sC,
                int M, int K, int N)
{
    const int BM = 128, BN = 128, BK = 32;
    __shared__ uint32_t As[BK][BM + 4];
    __shared__ uint32_t Bs[BK][BN + 4];

    int b = blockIdx.z;
    const float* Ab = A + (long)b * sA;
    const float* Xb = X + (long)b * sX;
    __half*      Cb = C + (long)b * sC;
    int m0 = blockIdx.y * BM, n0 = blockIdx.x * BN;
    int tid  = threadIdx.x;
    int wid  = tid >> 5, lane = tid & 31;
    int g4   = lane >> 2, q = lane & 3;
    int wm   = (wid >> 2) * 64;
    int wn   = (wid & 3) * 32;

    float acc[4][4][4];
#pragma unroll
    for (int i = 0; i < 4; i++)
#pragma unroll
        for (int j = 0; j < 4; j++)
#pragma unroll
            for (int r = 0; r < 4; r++) acc[i][j][r] = 0.f;

    for (int k0 = 0; k0 < K; k0 += BK) {
#pragma unroll
        for (int i = 0; i < 4; i++) {
            int f  = i * 256 + tid;
            int m  = f >> 3, k4 = (f & 7) << 2;
            float4 v = *(const float4*)&Ab[(long)(m0 + m) * K + k0 + k4];
            As[k4 + 0][m] = cvt_tf32(v.x); As[k4 + 1][m] = cvt_tf32(v.y);
            As[k4 + 2][m] = cvt_tf32(v.z); As[k4 + 3][m] = cvt_tf32(v.w);
        }
#pragma unroll
        for (int i = 0; i < 4; i++) {
            int f  = i * 256 + tid;
            int kk = f >> 5, n4 = (f & 31) << 2;
            float4 v = *(const float4*)&Xb[(long)(k0 + kk) * N + n0 + n4];
            uint4 u;
            u.x = cvt_tf32(v.x); u.y = cvt_tf32(v.y);
            u.z = cvt_tf32(v.z); u.w = cvt_tf32(v.w);
            *(uint4*)&Bs[kk][n4] = u;
        }
        __syncthreads();

#pragma unroll
        for (int ks = 0; ks < BK; ks += 8) {
            uint32_t af[4][4];
#pragma unroll
            for (int mf = 0; mf < 4; mf++) {
                int mb = wm + mf * 16;
                af[mf][0] = As[ks + q    ][mb + g4    ];
                af[mf][1] = As[ks + q    ][mb + g4 + 8];
                af[mf][2] = As[ks + q + 4][mb + g4    ];
                af[mf][3] = As[ks + q + 4][mb + g4 + 8];
            }
#pragma unroll
            for (int nf = 0; nf < 4; nf++) {
                int nb = wn + nf * 8;
                uint32_t b0 = Bs[ks + q    ][nb + g4];
                uint32_t b1 = Bs[ks + q + 4][nb + g4];
#pragma unroll
                for (int mf = 0; mf < 4; mf++) {
                    asm volatile(
                        "mma.sync.aligned.m16n8k8.row.col.f32.tf32.tf32.f32 "
                        "{%0,%1,%2,%3},{%4,%5,%6,%7},{%8,%9},{%0,%1,%2,%3};"
                        : "+f"(acc[mf][nf][0]), "+f"(acc[mf][nf][1]),
                          "+f"(acc[mf][nf][2]), "+f"(acc[mf][nf][3])
                        : "r"(af[mf][0]), "r"(af[mf][1]),
                          "r"(af[mf][2]), "r"(af[mf][3]),
                          "r"(b0), "r"(b1));
                }
            }
        }
        __syncthreads();
    }

#pragma unroll
    for (int mf = 0; mf < 4; mf++) {
        int mrow = m0 + wm + mf * 16 + g4;
#pragma unroll
        for (int nf = 0; nf < 4; nf++) {
            int nc = n0 + wn + nf * 8 + 2 * q;
            *(__half2*)&Cb[(long)mrow * N + nc] =
                __floats2half2_rn(acc[mf][nf][0], acc[mf][nf][1]);
            *(__half2*)&Cb[(long)(mrow + 8) * N + nc] =
                __floats2half2_rn(acc[mf][nf][2], acc[mf][nf][3]);
        }
    }
}

// ---------------- launch --------------------------------------------------
extern "C" void kernel_launch(void* const* d_in, const int* in_sizes, int n_in,
                              void* d_out, int out_size)
{
    const float *x = nullptr, *w_qkv = nullptr, *w_out = nullptr, *b_out = nullptr;
    for (int i = 0; i < n_in; i++) {
        const float* p = (const float*)d_in[i];
        if      (in_sizes[i] == BATCH * CIN * NPIX) x     = p;
        else if (in_sizes[i] == 3 * HID * CIN)      w_qkv = p;
        else if (in_sizes[i] == CIN * HID)          w_out = p;
        else if (in_sizes[i] == CIN)                b_out = p;
    }
    float* out = (float*)d_out;

    __half *xh, *wh, *wtoth;
    float *weff;
    cudaGetSymbolAddress((void**)&xh,    g_xh);
    cudaGetSymbolAddress((void**)&wh,    g_wh);
    cudaGetSymbolAddress((void**)&wtoth, g_wtoth);
    cudaGetSymbolAddress((void**)&weff,  g_weff);

    cudaFuncSetAttribute(k_fused1,
                         cudaFuncAttributeMaxDynamicSharedMemorySize, SMEM_F);
    cudaFuncSetAttribute(k_hgemm_ff,
                         cudaFuncAttributeMaxDynamicSharedMemorySize, SMEM_H);

    // 0) zero ALL accumulators + convert W_kv
    k_init<<<128, 256>>>(w_qkv + 128 * CIN);

    // 1) FUSED resident-W: kv-GEMM + exp + context + z; also emits fp16 x
    k_fused1<<<dim3(NPIX / 128 / F_NL, BATCH), 256, SMEM_F>>>(wh, x);

    // 2) P = ctxn^T @ W_q per head
    k_P<<<dim3(BATCH, HEADS), 1024>>>(w_qkv);

    // 3) wtot = w_out @ P  -> fp16 (A shared across batches: sA=0)
    k_sgemm_tc<<<dim3(2, 2, BATCH), 256>>>(
        w_out, 0,
        weff, (long)256 * HID,
        wtoth, (long)256 * 256,
        256, HID, 256);

    // 4) y[b] = W_total[b] @ x[b] + b_out  (resident-A fp16 GEMM)
    k_hgemm_ff<<<dim3(NPIX / 128 / H_NL, 2, BATCH), 256, SMEM_H>>>(
        wtoth, (long)256 * 256,
        xh, (long)CIN * NPIX,
        out, (long)256 * NPIX,
        b_out);
}

// round 16
// speedup vs baseline: 1.0950x; 1.0108x over previous
#include <cuda_runtime.h>
#include <cuda_fp16.h>
#include <math.h>
#include <stdint.h>

#define BATCH 8
#define CIN   256
#define NPIX  16384
#define HEADS 4
#define DH    32
#define HID   128

// ---------------- scratch (device globals; no allocation allowed) ------------
__device__ __half g_xh[(long)BATCH * CIN * NPIX];     // x in fp16 (written by k_fused1)
__device__ __half g_wh[256 * 256];                    // W_kv in fp16
__device__ __half g_wtoth[BATCH * 256 * 256];         // per-batch effective weight (fp16)
__device__ float  g_ctx[BATCH * HEADS * DH * DH];     // 32768
__device__ float  g_z[BATCH * HEADS * DH];            // 1024
__device__ float  g_weff[BATCH * 256 * HID];          // holds P[b][128][256]

__device__ __forceinline__ uint32_t smem_u32(const void* p) {
    uint32_t a;
    asm("{ .reg .u64 t; cvta.to.shared.u64 t, %1; cvt.u32.u64 %0, t; }" : "=r"(a) : "l"(p));
    return a;
}
#define CP16(dst, src) \
    asm volatile("cp.async.cg.shared.global [%0], [%1], 16;" :: "r"(dst), "l"(src) : "memory")
#define HMMA(acc, a0, a1, a2, a3, b0, b1) \
    asm volatile( \
        "mma.sync.aligned.m16n8k16.row.col.f32.f16.f16.f32 " \
        "{%0,%1,%2,%3},{%4,%5,%6,%7},{%8,%9},{%0,%1,%2,%3};" \
        : "+f"(acc[0]), "+f"(acc[1]), "+f"(acc[2]), "+f"(acc[3]) \
        : "r"(a0), "r"(a1), "r"(a2), "r"(a3), "r"(b0), "r"(b1))

// ---------------- init: zero ALL accumulators + convert W_kv to fp16 ---------
__global__ void k_init(const float* __restrict__ wkv) {
    int i = blockIdx.x * blockDim.x + threadIdx.x;   // 128*256 = 32768
    if (i < 16384) {
        float4 v = ((const float4*)wkv)[i];
        __half2 h0 = __floats2half2_rn(v.x, v.y);
        __half2 h1 = __floats2half2_rn(v.z, v.w);
        uint2 u = { *(uint32_t*)&h0, *(uint32_t*)&h1 };
        ((uint2*)g_wh)[i] = u;
    }
    g_ctx[i] = 0.f;
    if (i < BATCH * HEADS * DH) g_z[i] = 0.f;
}

// =============================================================================
// FUSED kernel (R11-exact, part of the 187.1us best run): kv-GEMM + context.
//   CTA: 256 ch x 128 px, K=256, 8 warps (4M x 2N), warp tile 64x64.
//   fp32-B direct-LDS fragment feed; emits fp16 x once; epilogue ctx mma.
// =============================================================================
#define F_AST   80
#define F_A_ST  (256 * F_AST)
#define F_BLDW  132
#define F_B_ST  (32 * F_BLDW * 4)
#define F_B_OFF (2 * F_A_ST)
#define SMEM_F  (F_B_OFF + 2 * F_B_ST)   // 74752
#define EV_LDH  136

__global__ __launch_bounds__(256, 1)
void k_fused1(const __half* __restrict__ W, const float* __restrict__ X)
{
    extern __shared__ char smem[];
    uint32_t sb = smem_u32(smem);
    int tid = threadIdx.x, wid = tid >> 5, lane = tid & 31;
    int g4 = lane >> 2, q = lane & 3;
    int rowoff = (lane & 7) + ((lane >> 3) & 1) * 8;
    int colsel = (lane >> 4) * 8;
    int b = blockIdx.y;
    long n0 = (long)blockIdx.x * 128;
    const float* Xb = X + (long)b * CIN * NPIX;
    __half* XHb = g_xh + (long)b * CIN * NPIX;

    int wm = (wid >> 1) * 64;   // 0,64,128,192 (ch)
    int wn = (wid & 1) * 64;    // 0,64 (px)

    float acc[4][8][4];
#pragma unroll
    for (int i = 0; i < 4; i++)
#pragma unroll
        for (int j = 0; j < 8; j++)
#pragma unroll
            for (int r = 0; r < 4; r++) acc[i][j][r] = 0.f;

#define F_LOAD(buf, k0) do {                                                    \
        uint32_t abase_ = sb + (buf) * F_A_ST;                                  \
        uint32_t bbase_ = sb + F_B_OFF + (buf) * F_B_ST;                        \
        _Pragma("unroll")                                                       \
        for (int i_ = 0; i_ < 4; i_++) {                                        \
            int f_ = i_ * 256 + tid;                                            \
            int r_ = f_ >> 2, c_ = f_ & 3;                                      \
            CP16(abase_ + r_ * F_AST + c_ * 16, W + (long)r_ * 256 + (k0) + c_ * 8); \
        }                                                                       \
        _Pragma("unroll")                                                       \
        for (int i_ = 0; i_ < 4; i_++) {                                        \
            int f_ = i_ * 256 + tid;                                            \
            int r_ = f_ >> 5, c_ = f_ & 31;                                     \
            CP16(bbase_ + r_ * (F_BLDW * 4) + c_ * 16,                          \
                 Xb + (long)((k0) + r_) * NPIX + n0 + c_ * 4);                  \
        }                                                                       \
        asm volatile("cp.async.commit_group;" ::: "memory");                    \
    } while (0)

    F_LOAD(0, 0);

#pragma unroll 1
    for (int t = 0; t < 8; t++) {
        if (t < 7) F_LOAD((t + 1) & 1, (t + 1) * 32);
        if (t < 7) { asm volatile("cp.async.wait_group 1;" ::: "memory"); }
        else       { asm volatile("cp.async.wait_group 0;" ::: "memory"); }
        __syncthreads();

        const float* Bst = (const float*)(smem + F_B_OFF + (t & 1) * F_B_ST);

        // ---- emit converted fp16 x tile (once per element)
#pragma unroll
        for (int i = 0; i < 2; i++) {
            int f = i * 256 + tid;
            int r = f >> 4, c = f & 15;
            const float* src = &Bst[r * F_BLDW + c * 8];
            uint4 u;
            __half2* uh = (__half2*)&u;
#pragma unroll
            for (int j = 0; j < 4; j++)
                uh[j] = __floats2half2_rn(src[2 * j], src[2 * j + 1]);
            *(uint4*)&XHb[(long)(t * 32 + r) * NPIX + n0 + c * 8] = u;
        }

        uint32_t abase = sb + (t & 1) * F_A_ST;
#pragma unroll
        for (int ks = 0; ks < 32; ks += 16) {
            uint32_t af[4][4];
#pragma unroll
            for (int mf = 0; mf < 4; mf++) {
                uint32_t addr = abase + (uint32_t)((wm + mf * 16 + rowoff) * F_AST
                                                   + (ks + colsel) * 2);
                asm volatile(
                    "ldmatrix.sync.aligned.m8n8.x4.shared.b16 {%0,%1,%2,%3}, [%4];"
                    : "=r"(af[mf][0]), "=r"(af[mf][1]), "=r"(af[mf][2]), "=r"(af[mf][3])
                    : "r"(addr));
            }
#pragma unroll
            for (int nf = 0; nf < 8; nf++) {
                int n = wn + nf * 8 + g4;
                float x0 = Bst[(ks + 2 * q)     * F_BLDW + n];
                float x1 = Bst[(ks + 2 * q + 1) * F_BLDW + n];
                float x2 = Bst[(ks + 2 * q + 8) * F_BLDW + n];
                float x3 = Bst[(ks + 2 * q + 9) * F_BLDW + n];
                __half2 hb0 = __floats2half2_rn(x0, x1);
                __half2 hb1 = __floats2half2_rn(x2, x3);
                uint32_t b0 = *(uint32_t*)&hb0;
                uint32_t b1 = *(uint32_t*)&hb1;
#pragma unroll
                for (int mf = 0; mf < 4; mf++)
                    HMMA(acc[mf][nf], af[mf][0], af[mf][1], af[mf][2], af[mf][3], b0, b1);
            }
        }
        __syncthreads();
    }

    // ===================== fused context epilogue =====================
    __half* EV = (__half*)smem;
    int isk = (wm < 128);
#pragma unroll
    for (int mf = 0; mf < 4; mf++) {
        int mrow = wm + mf * 16 + g4;
#pragma unroll
        for (int nf = 0; nf < 8; nf++) {
            int nc = wn + nf * 8 + 2 * q;
            float v0 = acc[mf][nf][0], v1 = acc[mf][nf][1];
            float v2 = acc[mf][nf][2], v3 = acc[mf][nf][3];
            if (isk) {
                v0 = __expf(v0); v1 = __expf(v1);
                v2 = __expf(v2); v3 = __expf(v3);
            }
            *(__half2*)&EV[mrow * EV_LDH + nc]       = __floats2half2_rn(v0, v1);
            *(__half2*)&EV[(mrow + 8) * EV_LDH + nc] = __floats2half2_rn(v2, v3);
        }
    }
    __syncthreads();

    int h = wid >> 1, p = wid & 1;
    const __half* Ek = EV + (h * 32) * EV_LDH;
    const __half* Vv = EV + (128 + h * 32) * EV_LDH;
    float c2[2][4][4];
    float z2[2][4];
#pragma unroll
    for (int i = 0; i < 2; i++) {
#pragma unroll
        for (int j = 0; j < 4; j++)
#pragma unroll
            for (int r = 0; r < 4; r++) c2[i][j][r] = 0.f;
#pragma unroll
        for (int r = 0; r < 4; r++) z2[i][r] = 0.f;
    }
    const uint32_t ONES = 0x3C003C00u;

#pragma unroll
    for (int ks = 0; ks < 64; ks += 16) {
        int fc = p * 64 + ks + 2 * q;
#pragma unroll
        for (int mf = 0; mf < 2; mf++) {
            int d0 = mf * 16 + g4;
            uint32_t a0 = *(const uint32_t*)&Ek[d0 * EV_LDH + fc];
            uint32_t a1 = *(const uint32_t*)&Ek[(d0 + 8) * EV_LDH + fc];
            uint32_t a2 = *(const uint32_t*)&Ek[d0 * EV_LDH + fc + 8];
            uint32_t a3 = *(const uint32_t*)&Ek[(d0 + 8) * EV_LDH + fc + 8];
            HMMA(z2[mf], a0, a1, a2, a3, ONES, ONES);
#pragma unroll
            for (int nf = 0; nf < 4; nf++) {
                int e0 = nf * 8 + g4;
                uint32_t b0 = *(const uint32_t*)&Vv[e0 * EV_LDH + fc];
                uint32_t b1 = *(const uint32_t*)&Vv[e0 * EV_LDH + fc + 8];
                HMMA(c2[mf][nf], a0, a1, a2, a3, b0, b1);
            }
        }
    }
    __syncthreads();

    if (q == 0) {
        float* zp = g_z + (b * HEADS + h) * DH;
        atomicAdd(&zp[g4],      z2[0][0]);
        atomicAdd(&zp[g4 + 8],  z2[0][2]);
        atomicAdd(&zp[g4 + 16], z2[1][0]);
        atomicAdd(&zp[g4 + 24], z2[1][2]);
    }

    float* red = (float*)smem + wid * 1024;
#pragma unroll
    for (int mf = 0; mf < 2; mf++)
#pragma unroll
        for (int nf = 0; nf < 4; nf++) {
            int dd = mf * 16 + g4, ee = nf * 8 + 2 * q;
            red[dd * 32 + ee]           = c2[mf][nf][0];
            red[dd * 32 + ee + 1]       = c2[mf][nf][1];
            red[(dd + 8) * 32 + ee]     = c2[mf][nf][2];
            red[(dd + 8) * 32 + ee + 1] = c2[mf][nf][3];
        }
    __syncthreads();

    const float* rall = (const float*)smem;
#pragma unroll
    for (int j = tid; j < 4096; j += 256) {
        int hh = j >> 10, e = j & 1023;
        float s = rall[(2 * hh) * 1024 + e] + rall[(2 * hh + 1) * 1024 + e];
        atomicAdd(&g_ctx[((long)b * HEADS + hh) * 1024 + e], s);
    }
}

// =============================================================================
// k_P: P[b][h*32+e][c] = sum_d (ctx[h][d][e]/z[d]) * W_q[h*32+d][c]
// grid (BATCH, HEADS), 1024 thr.
// =============================================================================
__global__ __launch_bounds__(1024)
void k_P(const float* __restrict__ wq)
{
    __shared__ float ctxn[32][33];
    __shared__ float zinv[32];
    int b = blockIdx.x, h = blockIdx.y;
    int tid = threadIdx.x;
    if (tid < 32) zinv[tid] = 1.0f / g_z[(b * HEADS + h) * DH + tid];
    __syncthreads();
    {
        int d = tid >> 5;
        ctxn[d][tid & 31] = g_ctx[((long)b * HEADS + h) * 1024 + tid] * zinv[d];
    }
    __syncthreads();

    int e  = tid >> 5;          // 0..31
    int c0 = (tid & 31) * 8;    // 8 cols per thread
    float s[8];
#pragma unroll
    for (int j = 0; j < 8; j++) s[j] = 0.f;

#pragma unroll 8
    for (int d = 0; d < 32; d++) {
        float a = ctxn[d][e];
        const float* wrow = wq + (h * 32 + d) * 256 + c0;
        float4 w0 = *(const float4*)&wrow[0];
        float4 w1 = *(const float4*)&wrow[4];
        s[0] = fmaf(a, w0.x, s[0]); s[1] = fmaf(a, w0.y, s[1]);
        s[2] = fmaf(a, w0.z, s[2]); s[3] = fmaf(a, w0.w, s[3]);
        s[4] = fmaf(a, w1.x, s[4]); s[5] = fmaf(a, w1.y, s[5]);
        s[6] = fmaf(a, w1.z, s[6]); s[7] = fmaf(a, w1.w, s[7]);
    }
    float* Pp = g_weff + (long)b * 32768 + (h * 32 + e) * 256 + c0;
    *(float4*)&Pp[0] = make_float4(s[0], s[1], s[2], s[3]);
    *(float4*)&Pp[4] = make_float4(s[4], s[5], s[6], s[7]);
}

// =============================================================================
// k_fold: wtot[b][o][c] = sum_he w_out[o][he] * P[b][he][c]   (fp16 out)
// grid (16 o-slabs, BATCH), 256 thr (thread = one c column, 16 o rows).
// w_out slab in smem (broadcast reads), P reads fully coalesced.
// Replaces the 13us tf32 sgemm with ~4us of plain FMA.
// =============================================================================
__global__ __launch_bounds__(256)
void k_fold(const float* __restrict__ w_out)
{
    __shared__ float ws[16][128];
    int o0 = blockIdx.x * 16, b = blockIdx.y;
    int tid = threadIdx.x;
    for (int i = tid; i < 16 * 128; i += 256) {
        int r = i >> 7, c = i & 127;
        ws[r][c] = w_out[(o0 + r) * HID + c];
    }
    __syncthreads();

    const float* Pb = g_weff + (long)b * 32768;
    float acc[16];
#pragma unroll
    for (int j = 0; j < 16; j++) acc[j] = 0.f;

#pragma unroll 4
    for (int he = 0; he < 128; he++) {
        float p = Pb[he * 256 + tid];
#pragma unroll
        for (int j = 0; j < 16; j++)
            acc[j] = fmaf(ws[j][he], p, acc[j]);
    }
    __half* Wt = g_wtoth + (long)b * 65536;
#pragma unroll
    for (int j = 0; j < 16; j++)
        Wt[(o0 + j) * 256 + tid] = __float2half_rn(acc[j]);
}

// =============================================================================
// fp16 x fp16 cp.async GEMM (R8-exact, part of the 187.1us best run)
// =============================================================================
#define H_A_BUF 18432
#define H_B_BUF 17408
#define SMEM_H (2 * H_A_BUF + 2 * H_B_BUF)

__device__ __forceinline__ void g2s_tile_ff(uint32_t sb, int buf,
                                            const __half* Arow, const __half* Xb,
                                            long n0, int k0) {
    int tid = threadIdx.x;
    uint32_t abase = sb + buf * H_A_BUF;
    uint32_t bbase = sb + 2 * H_A_BUF + buf * H_B_BUF;
#pragma unroll
    for (int i = 0; i < 4; i++) {
        int f = i * 256 + tid;
        int r = f >> 3, c = f & 7;
        CP16(abase + r * 144 + c * 16, Arow + (long)r * 256 + k0 + c * 8);
    }
#pragma unroll
    for (int i = 0; i < 4; i++) {
        int f = i * 256 + tid;
        int r = f >> 4, c = f & 15;
        CP16(bbase + r * 272 + c * 16, Xb + (long)(k0 + r) * NPIX + n0 + c * 8);
    }
    asm volatile("cp.async.commit_group;" ::: "memory");
}

__global__ __launch_bounds__(256, 2)
void k_hgemm_ff(const __half* __restrict__ A, long sA,
                const __half* __restrict__ X, long sX,
                float* __restrict__ C, long sC,
                const float* __restrict__ bias)
{
    extern __shared__ char smem[];
    uint32_t sb = smem_u32(smem);

    int b = blockIdx.z;
    const __half* Ab = A + (long)b * sA + (long)blockIdx.y * 128 * 256;
    const __half* Xb = X + (long)b * sX;
    long n0 = (long)blockIdx.x * 128;
    int m0 = blockIdx.y * 128;

    int tid  = threadIdx.x;
    int wid  = tid >> 5, lane = tid & 31;
    int g4   = lane >> 2, q = lane & 3;
    int wm   = (wid >> 2) * 64;
    int wn   = (wid & 3) * 32;
    int rowoff = (lane & 7) + ((lane >> 3) & 1) * 8;
    int colsel = (lane >> 4) * 8;

    float acc[4][4][4];
#pragma unroll
    for (int i = 0; i < 4; i++)
#pragma unroll
        for (int j = 0; j < 4; j++)
#pragma unroll
            for (int r = 0; r < 4; r++) acc[i][j][r] = 0.f;

    g2s_tile_ff(sb, 0, Ab, Xb, n0, 0);

#pragma unroll 1
    for (int t = 0; t < 4; t++) {
        if (t < 3) g2s_tile_ff(sb, (t + 1) & 1, Ab, Xb, n0, (t + 1) * 64);
        if (t < 3) { asm volatile("cp.async.wait_group 1;" ::: "memory"); }
        else       { asm volatile("cp.async.wait_group 0;" ::: "memory"); }
        __syncthreads();

        uint32_t abase = sb + (t & 1) * H_A_BUF;
        uint32_t bbase = sb + 2 * H_A_BUF + (t & 1) * H_B_BUF;
#pragma unroll
        for (int ks = 0; ks < 64; ks += 16) {
            uint32_t af[4][4];
#pragma unroll
            for (int mf = 0; mf < 4; mf++) {
                uint32_t addr = abase + (uint32_t)((wm + mf * 16 + rowoff) * 144
                                                   + (ks + colsel) * 2);
                asm volatile(
                    "ldmatrix.sync.aligned.m8n8.x4.shared.b16 {%0,%1,%2,%3}, [%4];"
                    : "=r"(af[mf][0]), "=r"(af[mf][1]), "=r"(af[mf][2]), "=r"(af[mf][3])
                    : "r"(addr));
            }
            uint32_t bf[2][4];
#pragma unroll
            for (int np = 0; np < 2; np++) {
                uint32_t addr = bbase + (uint32_t)((ks + rowoff) * 272
                                                   + (wn + np * 16 + colsel) * 2);
                asm volatile(
                    "ldmatrix.sync.aligned.m8n8.x4.trans.shared.b16 {%0,%1,%2,%3}, [%4];"
                    : "=r"(bf[np][0]), "=r"(bf[np][1]), "=r"(bf[np][2]), "=r"(bf[np][3])
                    : "r"(addr));
            }
#pragma unroll
            for (int nf = 0; nf < 4; nf++) {
                uint32_t b0 = bf[nf >> 1][(nf & 1) * 2];
                uint32_t b1 = bf[nf >> 1][(nf & 1) * 2 + 1];
#pragma unroll
                for (int mf = 0; mf < 4; mf++)
                    HMMA(acc[mf][nf], af[mf][0], af[mf][1], af[mf][2], af[mf][3], b0, b1);
            }
        }
        __syncthreads();
    }

#pragma unroll
    for (int mf = 0; mf < 4; mf++) {
        long mrow = m0 + wm + mf * 16 + g4;
        float bv0 = bias[mrow];
        float bv1 = bias[mrow + 8];
#pragma unroll
        for (int nf = 0; nf < 4; nf++) {
            long nc = n0 + wn + nf * 8 + 2 * q;
            float2 v0 = { acc[mf][nf][0] + bv0, acc[mf][nf][1] + bv0 };
            float2 v1 = { acc[mf][nf][2] + bv1, acc[mf][nf][3] + bv1 };
            float* Cf = C + (long)b * sC;
            *(float2*)&Cf[mrow * NPIX + nc]       = v0;
            *(float2*)&Cf[(mrow + 8) * NPIX + nc] = v1;
        }
    }
}

// ---------------- launch --------------------------------------------------
extern "C" void kernel_launch(void* const* d_in, const int* in_sizes, int n_in,
                              void* d_out, int out_size)
{
    const float *x = nullptr, *w_qkv = nullptr, *w_out = nullptr, *b_out = nullptr;
    for (int i = 0; i < n_in; i++) {
        const float* p = (const float*)d_in[i];
        if      (in_sizes[i] == BATCH * CIN * NPIX) x     = p;
        else if (in_sizes[i] == 3 * HID * CIN)      w_qkv = p;
        else if (in_sizes[i] == CIN * HID)          w_out = p;
        else if (in_sizes[i] == CIN)                b_out = p;
    }
    float* out = (float*)d_out;

    __half *xh, *wh, *wtoth;
    cudaGetSymbolAddress((void**)&xh,    g_xh);
    cudaGetSymbolAddress((void**)&wh,    g_wh);
    cudaGetSymbolAddress((void**)&wtoth, g_wtoth);

    cudaFuncSetAttribute(k_fused1,
                         cudaFuncAttributeMaxDynamicSharedMemorySize, SMEM_F);
    cudaFuncSetAttribute(k_hgemm_ff,
                         cudaFuncAttributeMaxDynamicSharedMemorySize, SMEM_H);

    // 0) zero ALL accumulators + convert W_kv
    k_init<<<128, 256>>>(w_qkv + 128 * CIN);

    // 1) FUSED: kv-GEMM + exp + context + z; also emits fp16 x (R11-exact)
    k_fused1<<<dim3(NPIX / 128, BATCH), 256, SMEM_F>>>(wh, x);

    // 2) P = ctxn^T @ W_q per head
    k_P<<<dim3(BATCH, HEADS), 1024>>>(w_qkv);

    // 3) wtot = w_out @ P  (lightweight FMA fold, fp16 out)
    k_fold<<<dim3(16, BATCH), 256>>>(w_out);

    // 4) y[b] = W_total[b] @ x[b] + b_out  (R8-exact fp16 GEMM)
    k_hgemm_ff<<<dim3(NPIX / 128, 2, BATCH), 256, SMEM_H>>>(
        wtoth, (long)256 * 256,
        xh, (long)CIN * NPIX,
        out, (long)256 * NPIX,
        b_out);
}

// round 17
// speedup vs baseline: 1.1206x; 1.0233x over previous
#include <cuda_runtime.h>
#include <cuda_fp16.h>
#include <math.h>
#include <stdint.h>

#define BATCH 8
#define CIN   256
#define NPIX  16384
#define HEADS 4
#define DH    32
#define HID   128

// ---------------- scratch (device globals; no allocation allowed) ------------
__device__ __half g_xh[(long)BATCH * CIN * NPIX];     // x in fp16 (written by k_fused1)
__device__ __half g_wh[256 * 256];                    // W_kv in fp16
__device__ __half g_wtoth[BATCH * 256 * 256];         // per-batch effective weight (fp16)
__device__ float  g_ctx[BATCH * HEADS * DH * DH];     // 32768
__device__ float  g_z[BATCH * HEADS * DH];            // 1024
__device__ float  g_weff[BATCH * 256 * HID];          // holds P[b][128][256]

__device__ __forceinline__ uint32_t smem_u32(const void* p) {
    uint32_t a;
    asm("{ .reg .u64 t; cvta.to.shared.u64 t, %1; cvt.u32.u64 %0, t; }" : "=r"(a) : "l"(p));
    return a;
}
#define CP16(dst, src) \
    asm volatile("cp.async.cg.shared.global [%0], [%1], 16;" :: "r"(dst), "l"(src) : "memory")
#define HMMA(acc, a0, a1, a2, a3, b0, b1) \
    asm volatile( \
        "mma.sync.aligned.m16n8k16.row.col.f32.f16.f16.f32 " \
        "{%0,%1,%2,%3},{%4,%5,%6,%7},{%8,%9},{%0,%1,%2,%3};" \
        : "+f"(acc[0]), "+f"(acc[1]), "+f"(acc[2]), "+f"(acc[3]) \
        : "r"(a0), "r"(a1), "r"(a2), "r"(a3), "r"(b0), "r"(b1))

// ---------------- init: zero ALL accumulators + convert W_kv to fp16 ---------
__global__ void k_init(const float* __restrict__ wkv) {
    int i = blockIdx.x * blockDim.x + threadIdx.x;   // 128*256 = 32768
    if (i < 16384) {
        float4 v = ((const float4*)wkv)[i];
        __half2 h0 = __floats2half2_rn(v.x, v.y);
        __half2 h1 = __floats2half2_rn(v.z, v.w);
        uint2 u = { *(uint32_t*)&h0, *(uint32_t*)&h1 };
        ((uint2*)g_wh)[i] = u;
    }
    g_ctx[i] = 0.f;
    if (i < BATCH * HEADS * DH) g_z[i] = 0.f;
}

// =============================================================================
// FUSED kernel (R11-exact): kv-GEMM + softmax-context; emits fp16 x.
// =============================================================================
#define F_AST   80
#define F_A_ST  (256 * F_AST)
#define F_BLDW  132
#define F_B_ST  (32 * F_BLDW * 4)
#define F_B_OFF (2 * F_A_ST)
#define SMEM_F  (F_B_OFF + 2 * F_B_ST)   // 74752
#define EV_LDH  136

__global__ __launch_bounds__(256, 1)
void k_fused1(const __half* __restrict__ W, const float* __restrict__ X)
{
    extern __shared__ char smem[];
    uint32_t sb = smem_u32(smem);
    int tid = threadIdx.x, wid = tid >> 5, lane = tid & 31;
    int g4 = lane >> 2, q = lane & 3;
    int rowoff = (lane & 7) + ((lane >> 3) & 1) * 8;
    int colsel = (lane >> 4) * 8;
    int b = blockIdx.y;
    long n0 = (long)blockIdx.x * 128;
    const float* Xb = X + (long)b * CIN * NPIX;
    __half* XHb = g_xh + (long)b * CIN * NPIX;

    int wm = (wid >> 1) * 64;
    int wn = (wid & 1) * 64;

    float acc[4][8][4];
#pragma unroll
    for (int i = 0; i < 4; i++)
#pragma unroll
        for (int j = 0; j < 8; j++)
#pragma unroll
            for (int r = 0; r < 4; r++) acc[i][j][r] = 0.f;

#define F_LOAD(buf, k0) do {                                                    \
        uint32_t abase_ = sb + (buf) * F_A_ST;                                  \
        uint32_t bbase_ = sb + F_B_OFF + (buf) * F_B_ST;                        \
        _Pragma("unroll")                                                       \
        for (int i_ = 0; i_ < 4; i_++) {                                        \
            int f_ = i_ * 256 + tid;                                            \
            int r_ = f_ >> 2, c_ = f_ & 3;                                      \
            CP16(abase_ + r_ * F_AST + c_ * 16, W + (long)r_ * 256 + (k0) + c_ * 8); \
        }                                                                       \
        _Pragma("unroll")                                                       \
        for (int i_ = 0; i_ < 4; i_++) {                                        \
            int f_ = i_ * 256 + tid;                                            \
            int r_ = f_ >> 5, c_ = f_ & 31;                                     \
            CP16(bbase_ + r_ * (F_BLDW * 4) + c_ * 16,                          \
                 Xb + (long)((k0) + r_) * NPIX + n0 + c_ * 4);                  \
        }                                                                       \
        asm volatile("cp.async.commit_group;" ::: "memory");                    \
    } while (0)

    F_LOAD(0, 0);

#pragma unroll 1
    for (int t = 0; t < 8; t++) {
        if (t < 7) F_LOAD((t + 1) & 1, (t + 1) * 32);
        if (t < 7) { asm volatile("cp.async.wait_group 1;" ::: "memory"); }
        else       { asm volatile("cp.async.wait_group 0;" ::: "memory"); }
        __syncthreads();

        const float* Bst = (const float*)(smem + F_B_OFF + (t & 1) * F_B_ST);

#pragma unroll
        for (int i = 0; i < 2; i++) {
            int f = i * 256 + tid;
            int r = f >> 4, c = f & 15;
            const float* src = &Bst[r * F_BLDW + c * 8];
            uint4 u;
            __half2* uh = (__half2*)&u;
#pragma unroll
            for (int j = 0; j < 4; j++)
                uh[j] = __floats2half2_rn(src[2 * j], src[2 * j + 1]);
            *(uint4*)&XHb[(long)(t * 32 + r) * NPIX + n0 + c * 8] = u;
        }

        uint32_t abase = sb + (t & 1) * F_A_ST;
#pragma unroll
        for (int ks = 0; ks < 32; ks += 16) {
            uint32_t af[4][4];
#pragma unroll
            for (int mf = 0; mf < 4; mf++) {
                uint32_t addr = abase + (uint32_t)((wm + mf * 16 + rowoff) * F_AST
                                                   + (ks + colsel) * 2);
                asm volatile(
                    "ldmatrix.sync.aligned.m8n8.x4.shared.b16 {%0,%1,%2,%3}, [%4];"
                    : "=r"(af[mf][0]), "=r"(af[mf][1]), "=r"(af[mf][2]), "=r"(af[mf][3])
                    : "r"(addr));
            }
#pragma unroll
            for (int nf = 0; nf < 8; nf++) {
                int n = wn + nf * 8 + g4;
                float x0 = Bst[(ks + 2 * q)     * F_BLDW + n];
                float x1 = Bst[(ks + 2 * q + 1) * F_BLDW + n];
                float x2 = Bst[(ks + 2 * q + 8) * F_BLDW + n];
                float x3 = Bst[(ks + 2 * q + 9) * F_BLDW + n];
                __half2 hb0 = __floats2half2_rn(x0, x1);
                __half2 hb1 = __floats2half2_rn(x2, x3);
                uint32_t b0 = *(uint32_t*)&hb0;
                uint32_t b1 = *(uint32_t*)&hb1;
#pragma unroll
                for (int mf = 0; mf < 4; mf++)
                    HMMA(acc[mf][nf], af[mf][0], af[mf][1], af[mf][2], af[mf][3], b0, b1);
            }
        }
        __syncthreads();
    }

    // ===================== fused context epilogue =====================
    __half* EV = (__half*)smem;
    int isk = (wm < 128);
#pragma unroll
    for (int mf = 0; mf < 4; mf++) {
        int mrow = wm + mf * 16 + g4;
#pragma unroll
        for (int nf = 0; nf < 8; nf++) {
            int nc = wn + nf * 8 + 2 * q;
            float v0 = acc[mf][nf][0], v1 = acc[mf][nf][1];
            float v2 = acc[mf][nf][2], v3 = acc[mf][nf][3];
            if (isk) {
                v0 = __expf(v0); v1 = __expf(v1);
                v2 = __expf(v2); v3 = __expf(v3);
            }
            *(__half2*)&EV[mrow * EV_LDH + nc]       = __floats2half2_rn(v0, v1);
            *(__half2*)&EV[(mrow + 8) * EV_LDH + nc] = __floats2half2_rn(v2, v3);
        }
    }
    __syncthreads();

    int h = wid >> 1, p = wid & 1;
    const __half* Ek = EV + (h * 32) * EV_LDH;
    const __half* Vv = EV + (128 + h * 32) * EV_LDH;
    float c2[2][4][4];
    float z2[2][4];
#pragma unroll
    for (int i = 0; i < 2; i++) {
#pragma unroll
        for (int j = 0; j < 4; j++)
#pragma unroll
            for (int r = 0; r < 4; r++) c2[i][j][r] = 0.f;
#pragma unroll
        for (int r = 0; r < 4; r++) z2[i][r] = 0.f;
    }
    const uint32_t ONES = 0x3C003C00u;

#pragma unroll
    for (int ks = 0; ks < 64; ks += 16) {
        int fc = p * 64 + ks + 2 * q;
#pragma unroll
        for (int mf = 0; mf < 2; mf++) {
            int d0 = mf * 16 + g4;
            uint32_t a0 = *(const uint32_t*)&Ek[d0 * EV_LDH + fc];
            uint32_t a1 = *(const uint32_t*)&Ek[(d0 + 8) * EV_LDH + fc];
            uint32_t a2 = *(const uint32_t*)&Ek[d0 * EV_LDH + fc + 8];
            uint32_t a3 = *(const uint32_t*)&Ek[(d0 + 8) * EV_LDH + fc + 8];
            HMMA(z2[mf], a0, a1, a2, a3, ONES, ONES);
#pragma unroll
            for (int nf = 0; nf < 4; nf++) {
                int e0 = nf * 8 + g4;
                uint32_t b0 = *(const uint32_t*)&Vv[e0 * EV_LDH + fc];
                uint32_t b1 = *(const uint32_t*)&Vv[e0 * EV_LDH + fc + 8];
                HMMA(c2[mf][nf], a0, a1, a2, a3, b0, b1);
            }
        }
    }
    __syncthreads();

    if (q == 0) {
        float* zp = g_z + (b * HEADS + h) * DH;
        atomicAdd(&zp[g4],      z2[0][0]);
        atomicAdd(&zp[g4 + 8],  z2[0][2]);
        atomicAdd(&zp[g4 + 16], z2[1][0]);
        atomicAdd(&zp[g4 + 24], z2[1][2]);
    }

    float* red = (float*)smem + wid * 1024;
#pragma unroll
    for (int mf = 0; mf < 2; mf++)
#pragma unroll
        for (int nf = 0; nf < 4; nf++) {
            int dd = mf * 16 + g4, ee = nf * 8 + 2 * q;
            red[dd * 32 + ee]           = c2[mf][nf][0];
            red[dd * 32 + ee + 1]       = c2[mf][nf][1];
            red[(dd + 8) * 32 + ee]     = c2[mf][nf][2];
            red[(dd + 8) * 32 + ee + 1] = c2[mf][nf][3];
        }
    __syncthreads();

    const float* rall = (const float*)smem;
#pragma unroll
    for (int j = tid; j < 4096; j += 256) {
        int hh = j >> 10, e = j & 1023;
        float s = rall[(2 * hh) * 1024 + e] + rall[(2 * hh + 1) * 1024 + e];
        atomicAdd(&g_ctx[((long)b * HEADS + hh) * 1024 + e], s);
    }
}

// =============================================================================
// k_P: P[b][h*32+e][c] = sum_d (ctx[h][d][e]/z[d]) * W_q[h*32+d][c]
// grid (BATCH, HEADS), 1024 thr.
// =============================================================================
__global__ __launch_bounds__(1024)
void k_P(const float* __restrict__ wq)
{
    __shared__ float ctxn[32][33];
    __shared__ float zinv[32];
    int b = blockIdx.x, h = blockIdx.y;
    int tid = threadIdx.x;
    if (tid < 32) zinv[tid] = 1.0f / g_z[(b * HEADS + h) * DH + tid];
    __syncthreads();
    {
        int d = tid >> 5;
        ctxn[d][tid & 31] = g_ctx[((long)b * HEADS + h) * 1024 + tid] * zinv[d];
    }
    __syncthreads();

    int e  = tid >> 5;
    int c0 = (tid & 31) * 8;
    float s[8];
#pragma unroll
    for (int j = 0; j < 8; j++) s[j] = 0.f;

#pragma unroll 8
    for (int d = 0; d < 32; d++) {
        float a = ctxn[d][e];
        const float* wrow = wq + (h * 32 + d) * 256 + c0;
        float4 w0 = *(const float4*)&wrow[0];
        float4 w1 = *(const float4*)&wrow[4];
        s[0] = fmaf(a, w0.x, s[0]); s[1] = fmaf(a, w0.y, s[1]);
        s[2] = fmaf(a, w0.z, s[2]); s[3] = fmaf(a, w0.w, s[3]);
        s[4] = fmaf(a, w1.x, s[4]); s[5] = fmaf(a, w1.y, s[5]);
        s[6] = fmaf(a, w1.z, s[6]); s[7] = fmaf(a, w1.w, s[7]);
    }
    float* Pp = g_weff + (long)b * 32768 + (h * 32 + e) * 256 + c0;
    *(float4*)&Pp[0] = make_float4(s[0], s[1], s[2], s[3]);
    *(float4*)&Pp[4] = make_float4(s[4], s[5], s[6], s[7]);
}

// =============================================================================
// k_fold: wtot[b][o][c] = sum_he w_out[o][he] * P[b][he][c]   (fp16 out)
// grid (64 o-slabs, BATCH) = 512 blocks, 256 thr; 4 o-rows per block.
// (R16's 128-block version was latency-bound at 24us; 4x more blocks.)
// =============================================================================
__global__ __launch_bounds__(256)
void k_fold(const float* __restrict__ w_out)
{
    __shared__ float ws[4][128];
    int o0 = blockIdx.x * 4, b = blockIdx.y;
    int tid = threadIdx.x;
    if (tid < 128) {
#pragma unroll
        for (int r = 0; r < 4; r++)
            ws[r][tid] = w_out[(o0 + r) * HID + tid];
    }
    __syncthreads();

    const float* Pb = g_weff + (long)b * 32768;
    float acc[4] = {0.f, 0.f, 0.f, 0.f};

#pragma unroll 8
    for (int he = 0; he < 128; he++) {
        float p = Pb[he * 256 + tid];
        acc[0] = fmaf(ws[0][he], p, acc[0]);
        acc[1] = fmaf(ws[1][he], p, acc[1]);
        acc[2] = fmaf(ws[2][he], p, acc[2]);
        acc[3] = fmaf(ws[3][he], p, acc[3]);
    }
    __half* Wt = g_wtoth + (long)b * 65536;
#pragma unroll
    for (int j = 0; j < 4; j++)
        Wt[(o0 + j) * 256 + tid] = __float2half_rn(acc[j]);
}

// =============================================================================
// fp16 x fp16 cp.async GEMM (R8-exact)
// =============================================================================
#define H_A_BUF 18432
#define H_B_BUF 17408
#define SMEM_H (2 * H_A_BUF + 2 * H_B_BUF)

__device__ __forceinline__ void g2s_tile_ff(uint32_t sb, int buf,
                                            const __half* Arow, const __half* Xb,
                                            long n0, int k0) {
    int tid = threadIdx.x;
    uint32_t abase = sb + buf * H_A_BUF;
    uint32_t bbase = sb + 2 * H_A_BUF + buf * H_B_BUF;
#pragma unroll
    for (int i = 0; i < 4; i++) {
        int f = i * 256 + tid;
        int r = f >> 3, c = f & 7;
        CP16(abase + r * 144 + c * 16, Arow + (long)r * 256 + k0 + c * 8);
    }
#pragma unroll
    for (int i = 0; i < 4; i++) {
        int f = i * 256 + tid;
        int r = f >> 4, c = f & 15;
        CP16(bbase + r * 272 + c * 16, Xb + (long)(k0 + r) * NPIX + n0 + c * 8);
    }
    asm volatile("cp.async.commit_group;" ::: "memory");
}

__global__ __launch_bounds__(256, 2)
void k_hgemm_ff(const __half* __restrict__ A, long sA,
                const __half* __restrict__ X, long sX,
                float* __restrict__ C, long sC,
                const float* __restrict__ bias)
{
    extern __shared__ char smem[];
    uint32_t sb = smem_u32(smem);

    int b = blockIdx.z;
    const __half* Ab = A + (long)b * sA + (long)blockIdx.y * 128 * 256;
    const __half* Xb = X + (long)b * sX;
    long n0 = (long)blockIdx.x * 128;
    int m0 = blockIdx.y * 128;

    int tid  = threadIdx.x;
    int wid  = tid >> 5, lane = tid & 31;
    int g4   = lane >> 2, q = lane & 3;
    int wm   = (wid >> 2) * 64;
    int wn   = (wid & 3) * 32;
    int rowoff = (lane & 7) + ((lane >> 3) & 1) * 8;
    int colsel = (lane >> 4) * 8;

    float acc[4][4][4];
#pragma unroll
    for (int i = 0; i < 4; i++)
#pragma unroll
        for (int j = 0; j < 4; j++)
#pragma unroll
            for (int r = 0; r < 4; r++) acc[i][j][r] = 0.f;

    g2s_tile_ff(sb, 0, Ab, Xb, n0, 0);

#pragma unroll 1
    for (int t = 0; t < 4; t++) {
        if (t < 3) g2s_tile_ff(sb, (t + 1) & 1, Ab, Xb, n0, (t + 1) * 64);
        if (t < 3) { asm volatile("cp.async.wait_group 1;" ::: "memory"); }
        else       { asm volatile("cp.async.wait_group 0;" ::: "memory"); }
        __syncthreads();

        uint32_t abase = sb + (t & 1) * H_A_BUF;
        uint32_t bbase = sb + 2 * H_A_BUF + (t & 1) * H_B_BUF;
#pragma unroll
        for (int ks = 0; ks < 64; ks += 16) {
            uint32_t af[4][4];
#pragma unroll
            for (int mf = 0; mf < 4; mf++) {
                uint32_t addr = abase + (uint32_t)((wm + mf * 16 + rowoff) * 144
                                                   + (ks + colsel) * 2);
                asm volatile(
                    "ldmatrix.sync.aligned.m8n8.x4.shared.b16 {%0,%1,%2,%3}, [%4];"
                    : "=r"(af[mf][0]), "=r"(af[mf][1]), "=r"(af[mf][2]), "=r"(af[mf][3])
                    : "r"(addr));
            }
            uint32_t bf[2][4];
#pragma unroll
            for (int np = 0; np < 2; np++) {
                uint32_t addr = bbase + (uint32_t)((ks + rowoff) * 272
                                                   + (wn + np * 16 + colsel) * 2);
                asm volatile(
                    "ldmatrix.sync.aligned.m8n8.x4.trans.shared.b16 {%0,%1,%2,%3}, [%4];"
                    : "=r"(bf[np][0]), "=r"(bf[np][1]), "=r"(bf[np][2]), "=r"(bf[np][3])
                    : "r"(addr));
            }
#pragma unroll
            for (int nf = 0; nf < 4; nf++) {
                uint32_t b0 = bf[nf >> 1][(nf & 1) * 2];
                uint32_t b1 = bf[nf >> 1][(nf & 1) * 2 + 1];
#pragma unroll
                for (int mf = 0; mf < 4; mf++)
                    HMMA(acc[mf][nf], af[mf][0], af[mf][1], af[mf][2], af[mf][3], b0, b1);
            }
        }
        __syncthreads();
    }

#pragma unroll
    for (int mf = 0; mf < 4; mf++) {
        long mrow = m0 + wm + mf * 16 + g4;
        float bv0 = bias[mrow];
        float bv1 = bias[mrow + 8];
#pragma unroll
        for (int nf = 0; nf < 4; nf++) {
            long nc = n0 + wn + nf * 8 + 2 * q;
            float2 v0 = { acc[mf][nf][0] + bv0, acc[mf][nf][1] + bv0 };
            float2 v1 = { acc[mf][nf][2] + bv1, acc[mf][nf][3] + bv1 };
            float* Cf = C + (long)b * sC;
            *(float2*)&Cf[mrow * NPIX + nc]       = v0;
            *(float2*)&Cf[(mrow + 8) * NPIX + nc] = v1;
        }
    }
}

// ---------------- launch --------------------------------------------------
extern "C" void kernel_launch(void* const* d_in, const int* in_sizes, int n_in,
                              void* d_out, int out_size)
{
    const float *x = nullptr, *w_qkv = nullptr, *w_out = nullptr, *b_out = nullptr;
    for (int i = 0; i < n_in; i++) {
        const float* p = (const float*)d_in[i];
        if      (in_sizes[i] == BATCH * CIN * NPIX) x     = p;
        else if (in_sizes[i] == 3 * HID * CIN)      w_qkv = p;
        else if (in_sizes[i] == CIN * HID)          w_out = p;
        else if (in_sizes[i] == CIN)                b_out = p;
    }
    float* out = (float*)d_out;

    __half *xh, *wh, *wtoth;
    cudaGetSymbolAddress((void**)&xh,    g_xh);
    cudaGetSymbolAddress((void**)&wh,    g_wh);
    cudaGetSymbolAddress((void**)&wtoth, g_wtoth);

    cudaFuncSetAttribute(k_fused1,
                         cudaFuncAttributeMaxDynamicSharedMemorySize, SMEM_F);
    cudaFuncSetAttribute(k_hgemm_ff,
                         cudaFuncAttributeMaxDynamicSharedMemorySize, SMEM_H);

    // 0) zero ALL accumulators + convert W_kv
    k_init<<<128, 256>>>(w_qkv + 128 * CIN);

    // 1) FUSED: kv-GEMM + exp + context + z; also emits fp16 x (R11-exact)
    k_fused1<<<dim3(NPIX / 128, BATCH), 256, SMEM_F>>>(wh, x);

    // 2) P = ctxn^T @ W_q per head
    k_P<<<dim3(BATCH, HEADS), 1024>>>(w_qkv);

    // 3) wtot = w_out @ P  (512-block FMA fold, fp16 out)
    k_fold<<<dim3(64, BATCH), 256>>>(w_out);

    // 4) y[b] = W_total[b] @ x[b] + b_out  (R8-exact fp16 GEMM)
    k_hgemm_ff<<<dim3(NPIX / 128, 2, BATCH), 256, SMEM_H>>>(
        wtoth, (long)256 * 256,
        xh, (long)CIN * NPIX,
        out, (long)256 * NPIX,
        b_out);
}